// round 12
// baseline (speedup 1.0000x reference)
#include <cuda_runtime.h>
#include <cuda_fp16.h>
#include <cstdint>

#define BB 2
#define CC 32
#define HH 128
#define WW 416
#define DD 48
#define HW_ (HH*WW)
#define CHW_ (CC*HH*WW)
#define ISCALE 0.05892556509887896f  // 1/sqrt(C*K2) = 1/sqrt(288)
#define RP 416    // row stride (halves) for fm16/Al16/Br16 (832B, 16B-aligned)
#define PHW 208   // parity half-width

// Emulate the reference's fp16 cast, stored as float32.
__device__ __forceinline__ float h16(float v) {
    return __half2float(__float2half_rn(v));
}

#define MMA16816(c0,c1,c2,c3,a0,a1,a2,a3,b0,b1) \
  asm volatile("mma.sync.aligned.m16n8k16.row.col.f32.f16.f16.f32 " \
    "{%0,%1,%2,%3}, {%4,%5,%6,%7}, {%8,%9}, {%0,%1,%2,%3};" \
    : "+f"(c0), "+f"(c1), "+f"(c2), "+f"(c3) \
    : "r"(a0), "r"(a1), "r"(a2), "r"(a3), "r"(b0), "r"(b1))

#define TWH 40   // operand row stride in halves
#define TWW 20   // in 32-bit words

// Device-global scratch (allocation forbidden)
__device__ __half g_Al16[BB*CC*HH*RP];     // normalized box sums, fp16
__device__ __half g_Br16[BB*CC*HH*RP];
__device__ __half g_fm16[BB*CC*HH*RP];     // normalized xm * ISCALE, fp16
__device__ __half g_xl16[BB*CC*HH*2*PHW];  // parity-split fp16 inputs
__device__ __half g_xr16[BB*CC*HH*2*PHW];
__device__ float  g_nli[BB*HW_];
__device__ float  g_nri[BB*HW_];
__device__ float  g_Grow[BB*DD*HW_];

// ---------------------------------------------------------------------------
// Kernel 1: prep. z=0/1: box sums + norms + parity-split fp16 input copies.
// z=2: per-pixel channel-normalized xm (ISCALE folded) as fp16.
// ---------------------------------------------------------------------------
__global__ __launch_bounds__(448) void cv_prep_kernel(
    const float* __restrict__ xl, const float* __restrict__ xm,
    const float* __restrict__ xr)
{
    const int t    = threadIdx.x;
    const int wi   = t >> 5;
    const int lane = t & 31;
    const int h    = blockIdx.x;
    const int b    = blockIdx.y;
    const int img  = blockIdx.z;

    const int u = wi*30 + lane - 1;          // -1 .. 419
    const bool vu = (u >= 0) && (u < WW);
    const bool writer = (lane >= 1) && (lane <= 30) && (u < WW);

    if (img == 2) {
        if (writer) {
            float ss = 0.f;
            float fv[CC];
            const float* pm = xm + b*CHW_ + h*WW + u;
            #pragma unroll
            for (int c = 0; c < CC; c++) { fv[c] = __ldg(pm + c*HW_); ss += fv[c]*fv[c]; }
            float nf = ISCALE / fmaxf(sqrtf(ss), 1e-3f);
            #pragma unroll
            for (int c = 0; c < CC; c++)
                g_fm16[((b*CC + c)*HH + h)*RP + u] = __float2half_rn(fv[c]*nf);
        }
        return;
    }

    const float* x = img ? xr : xl;
    __half* gbox   = img ? g_Br16 : g_Al16;
    __half* gq     = img ? g_xr16 : g_xl16;
    float* gn      = img ? g_nri : g_nli;

    const bool h0 = (h > 0), h1 = (h < HH - 1);
    const float* base = x + b*CHW_ + h*WW + (vu ? u : 0);

    float ssum = 0.f;
    float boxv[CC];
    #pragma unroll
    for (int c = 0; c < CC; c++) {
        float r0 = (vu && h0) ? __ldg(base + c*HW_ - WW) : 0.f;
        float r1 =  vu        ? __ldg(base + c*HW_)      : 0.f;
        float r2 = (vu && h1) ? __ldg(base + c*HW_ + WW) : 0.f;
        float cs = r0 + r1 + r2;
        ssum += r0*r0 + r1*r1 + r2*r2;
        if (writer)
            gq[((b*CC + c)*HH + h)*(2*PHW) + (u & 1)*PHW + (u >> 1)] = __float2half_rn(r1);
        float csl = __shfl_up_sync(0xffffffffu, cs, 1);
        float csr = __shfl_down_sync(0xffffffffu, cs, 1);
        boxv[c] = csl + cs + csr;
    }
    float sql = __shfl_up_sync(0xffffffffu, ssum, 1);
    float sqr = __shfl_down_sync(0xffffffffu, ssum, 1);
    float ni = 1.f / fmaxf(sqrtf(sql + ssum + sqr), 1e-3f);

    if (writer) {
        #pragma unroll
        for (int c = 0; c < CC; c++)
            gbox[((b*CC + c)*HH + h)*RP + u] = __float2half_rn(boxv[c] * ni);
        gn[b*HW_ + h*WW + u] = ni;
    }
}

// ---------------------------------------------------------------------------
// Kernel 2: Grow via HMMA on parity-split inputs.
// G(2p+q, d) = sum_c XLq[p] * XRq[p-d].  Staging [d][u_loc], 3-tap copy-out.
// Dynamic smem: XL 2*120*40 + XR 2*168*40 + G 48*264 halves = 71424 B.
// ---------------------------------------------------------------------------
#define GP 120
#define GJ 168
#define US 264

__global__ __launch_bounds__(256) void cv_g_kernel()
{
    extern __shared__ __half gsm[];
    __half* s_XL = gsm;                            // [q][p_loc][c]
    __half* s_XR = gsm + 2*GP*TWH;                 // [q][j][c]
    __half* s_G  = gsm + 2*GP*TWH + 2*GJ*TWH;      // [d][u_loc]

    const int t  = threadIdx.x;
    const int u0 = blockIdx.x * 208;
    const int r  = blockIdx.y;
    const int b  = blockIdx.z;
    const int P0 = u0/2 - 8;          // multiple of 8
    const int J0 = P0 - 48;           // multiple of 8

    // XL fill: 2 parities x 32 c x 15 vectors (no straddles; OOB -> zero)
    for (int i = t; i < 2*CC*15; i += 256) {
        int k = i % 15, c = (i/15) % CC, q = i / (15*CC);
        int p = P0 + 8*k;
        int4 v = make_int4(0,0,0,0);
        if (p >= 0 && p <= PHW-8)
            v = *(const int4*)&g_xl16[((b*CC + c)*HH + r)*(2*PHW) + q*PHW + p];
        const __half* hv = (const __half*)&v;
        __half* dst = s_XL + q*GP*TWH + (8*k)*TWH + c;
        #pragma unroll
        for (int m = 0; m < 8; m++) dst[m*TWH] = hv[m];
    }
    // XR fill: 2 x 32 x 21 vectors
    for (int i = t; i < 2*CC*21; i += 256) {
        int k = i % 21, c = (i/21) % CC, q = i / (21*CC);
        int m0 = J0 + 8*k;
        int4 v = make_int4(0,0,0,0);
        if (m0 >= 0 && m0 <= PHW-8)
            v = *(const int4*)&g_xr16[((b*CC + c)*HH + r)*(2*PHW) + q*PHW + m0];
        const __half* hv = (const __half*)&v;
        __half* dst = s_XR + q*GJ*TWH + (8*k)*TWH + c;
        #pragma unroll
        for (int m = 0; m < 8; m++) dst[m*TWH] = hv[m];
    }
    __syncthreads();

    const int wid  = t >> 5;
    const int lane = t & 31;
    const int g    = lane >> 2;
    const int tt   = lane & 3;

    for (int job = wid; job < 16; job += 8) {
        const int q = job & 1;
        const int i = job >> 1;                   // m-tile 0..7
        const uint32_t* XLw = (const uint32_t*)(s_XL + q*GP*TWH);
        const uint32_t* XRw = (const uint32_t*)(s_XR + q*GJ*TWH);

        const int rl0 = 16*i + g, rl1 = rl0 + 8;  // p_loc rows
        const int ra = rl0 * TWW + tt;
        const int rb = ra + 8 * TWW;
        const uint32_t a0 = XLw[ra],   a1 = XLw[rb],   a2 = XLw[ra+4],  a3 = XLw[rb+4];
        const uint32_t a4 = XLw[ra+8], a5 = XLw[rb+8], a6 = XLw[ra+12], a7 = XLw[rb+12];

        const int ub0 = 2*rl0 + q;                // u_loc of rl0
        const int ub1 = 2*rl1 + q;

        #pragma unroll
        for (int nn = 0; nn < 8; nn++) {
            const int jr = 16*i + 8*nn;
            const int jb = (jr + g) * TWW + tt;
            const int j0 = jr + 2*tt, j1 = j0 + 1;
            uint32_t b0 = XRw[jb], b1 = XRw[jb+4], b2 = XRw[jb+8], b3 = XRw[jb+12];
            float c0 = 0.f, c1 = 0.f, c2 = 0.f, c3 = 0.f;
            MMA16816(c0,c1,c2,c3, a0,a1,a2,a3, b0,b1);
            MMA16816(c0,c1,c2,c3, a4,a5,a6,a7, b2,b3);
            int d;
            d = rl0 + 48 - j0; if (d >= 0 && d < DD) s_G[d*US + ub0] = __float2half_rn(c0);
            d = rl0 + 48 - j1; if (d >= 0 && d < DD) s_G[d*US + ub0] = __float2half_rn(c1);
            d = rl1 + 48 - j0; if (d >= 0 && d < DD) s_G[d*US + ub1] = __float2half_rn(c2);
            d = rl1 + 48 - j1; if (d >= 0 && d < DD) s_G[d*US + ub1] = __float2half_rn(c3);
        }
    }
    __syncthreads();

    // Horizontal 3-tap + vectorized store. u = u0 + ul, u_loc = ul + 16.
    for (int i = t; i < DD*52; i += 256) {
        int d = i / 52, k4 = (i % 52) * 4;
        int base = d*US + 16 + k4;                 // even
        __half2 q0 = *(const __half2*)(s_G + base - 2);
        __half2 q1 = *(const __half2*)(s_G + base);
        __half2 q2 = *(const __half2*)(s_G + base + 2);
        __half2 q3 = *(const __half2*)(s_G + base + 4);
        float gm1 = __high2float(q0);
        float g0  = __low2float(q1), g1 = __high2float(q1);
        float g2  = __low2float(q2), g3 = __high2float(q2);
        float g4  = __low2float(q3);
        float4 o;
        o.x = gm1 + g0 + g1;
        o.y = g0 + g1 + g2;
        o.z = g1 + g2 + g3;
        o.w = g2 + g3 + g4;
        *(float4*)&g_Grow[(b*DD + d)*HW_ + r*WW + u0 + k4] = o;
    }
}

// ---------------------------------------------------------------------------
// Kernel 3: LR channel -- vertical 3-tap over Grow + normalization (proven).
// ---------------------------------------------------------------------------
__global__ __launch_bounds__(416) void cv_lr_out_kernel(float* __restrict__ out)
{
    const int w  = threadIdx.x;
    const int h0 = blockIdx.x * 4;
    const int d  = blockIdx.y;
    const int b  = blockIdx.z;

    const int ob = (b*3 + 2)*DD*HW_ + d*HW_ + w;
    if (w < d || w >= WW - d) {
        #pragma unroll
        for (int r = 0; r < 4; r++) out[ob + (h0+r)*WW] = 0.f;
        return;
    }
    const int u = w + d;
    const float* gb = g_Grow + (b*DD + d)*HW_ + u;

    float v[6];
    #pragma unroll
    for (int r = 0; r < 6; r++) {
        int row = h0 - 1 + r;
        v[r] = (row >= 0 && row < HH) ? __ldg(gb + row*WW) : 0.f;
    }
    const float* pnl = g_nli + b*HW_ + u;
    const float* pnr = g_nri + b*HW_ + (w - d);
    #pragma unroll
    for (int r = 0; r < 4; r++) {
        int h = h0 + r;
        float s = v[r] + v[r+1] + v[r+2];
        float val = s * __ldg(pnl + h*WW) * __ldg(pnr + h*WW) * ISCALE;
        out[ob + h*WW] = h16(fminf(fmaxf(val, -10.f), 10.f));
    }
}

// ---------------------------------------------------------------------------
// Kernel 4: L/R channels via HMMA. Vector fills from fp16 artifacts,
// staging [dp][w] (WS=136), vectorized copy-out.
// Dynamic smem: (128+176+176)*40 + 96*136 halves = 64512 B.
// ---------------------------------------------------------------------------
#define WS 136

__global__ __launch_bounds__(256) void cv_lrcost_kernel(float* __restrict__ out)
{
    extern __shared__ __half lsm[];
    __half* s_F  = lsm;                      // [w_local][c]
    __half* s_WA = lsm + 128*TWH;            // [j][c], A' at col u0+j
    __half* s_WB = lsm + (128+176)*TWH;      // [j][c], B' at col u0-48+j
    __half* s_S  = lsm + (128+176+176)*TWH;  // [dp][w]

    const int t  = threadIdx.x;
    const int u0 = blockIdx.x * 128;
    const int h  = blockIdx.y;
    const int b  = blockIdx.z;

    // F fill: 32 c x 16 vectors
    for (int i = t; i < CC*16; i += 256) {
        int c = i >> 4, k = i & 15;
        int col = u0 + 8*k;
        int4 v = make_int4(0,0,0,0);
        if (col <= WW-8) v = *(const int4*)&g_fm16[((b*CC + c)*HH + h)*RP + col];
        const __half* hv = (const __half*)&v;
        __half* dst = s_F + (8*k)*TWH + c;
        #pragma unroll
        for (int m = 0; m < 8; m++) dst[m*TWH] = hv[m];
    }
    // WA fill: 32 c x 22 vectors
    for (int i = t; i < CC*22; i += 256) {
        int c = i / 22, k = i % 22;
        int col = u0 + 8*k;
        int4 v = make_int4(0,0,0,0);
        if (col <= WW-8) v = *(const int4*)&g_Al16[((b*CC + c)*HH + h)*RP + col];
        const __half* hv = (const __half*)&v;
        __half* dst = s_WA + (8*k)*TWH + c;
        #pragma unroll
        for (int m = 0; m < 8; m++) dst[m*TWH] = hv[m];
    }
    // WB fill: 32 c x 22 vectors
    for (int i = t; i < CC*22; i += 256) {
        int c = i / 22, k = i % 22;
        int col = u0 - 48 + 8*k;
        int4 v = make_int4(0,0,0,0);
        if (col >= 0 && col <= WW-8)
            v = *(const int4*)&g_Br16[((b*CC + c)*HH + h)*RP + col];
        const __half* hv = (const __half*)&v;
        __half* dst = s_WB + (8*k)*TWH + c;
        #pragma unroll
        for (int m = 0; m < 8; m++) dst[m*TWH] = hv[m];
    }
    __syncthreads();

    const int wid  = t >> 5;
    const int lane = t & 31;
    const int g    = lane >> 2;
    const int tt   = lane & 3;
    const int wl0  = wid * 16;

    const uint32_t* Fw  = (const uint32_t*)s_F;
    const uint32_t* WAw = (const uint32_t*)s_WA;
    const uint32_t* WBw = (const uint32_t*)s_WB;

    const int rl0 = wl0 + g, rl1 = rl0 + 8;
    const int ra = rl0 * TWW + tt;
    const int rb = ra + 8 * TWW;
    const uint32_t a0 = Fw[ra],    a1 = Fw[rb],    a2 = Fw[ra+4],  a3 = Fw[rb+4];
    const uint32_t a4 = Fw[ra+8],  a5 = Fw[rb+8],  a6 = Fw[ra+12], a7 = Fw[rb+12];

    #pragma unroll
    for (int nn = 0; nn < 8; nn++) {
        const int jr = wl0 + 8*nn;
        const int jb = (jr + g) * TWW + tt;
        const int j0 = jr + 2*tt, j1 = j0 + 1;

        {   // L side: dp = j - rl
            uint32_t b0 = WAw[jb], b1 = WAw[jb+4], b2 = WAw[jb+8], b3 = WAw[jb+12];
            float c0 = 0.f, c1 = 0.f, c2 = 0.f, c3 = 0.f;
            MMA16816(c0,c1,c2,c3, a0,a1,a2,a3, b0,b1);
            MMA16816(c0,c1,c2,c3, a4,a5,a6,a7, b2,b3);
            int d;
            d = j0 - rl0; if (d >= 0 && d < DD)
                s_S[d*WS + rl0] = __float2half_rn(fminf(fmaxf(c0, -10.f), 10.f));
            d = j1 - rl0; if (d >= 0 && d < DD)
                s_S[d*WS + rl0] = __float2half_rn(fminf(fmaxf(c1, -10.f), 10.f));
            d = j0 - rl1; if (d >= 0 && d < DD)
                s_S[d*WS + rl1] = __float2half_rn(fminf(fmaxf(c2, -10.f), 10.f));
            d = j1 - rl1; if (d >= 0 && d < DD)
                s_S[d*WS + rl1] = __float2half_rn(fminf(fmaxf(c3, -10.f), 10.f));
        }
        {   // R side: dp = 48 + (rl + 48 - j)
            uint32_t b0 = WBw[jb], b1 = WBw[jb+4], b2 = WBw[jb+8], b3 = WBw[jb+12];
            float c0 = 0.f, c1 = 0.f, c2 = 0.f, c3 = 0.f;
            MMA16816(c0,c1,c2,c3, a0,a1,a2,a3, b0,b1);
            MMA16816(c0,c1,c2,c3, a4,a5,a6,a7, b2,b3);
            int d;
            d = rl0 + 48 - j0; if (d >= 0 && d < DD)
                s_S[(48+d)*WS + rl0] = __float2half_rn(fminf(fmaxf(c0, -10.f), 10.f));
            d = rl0 + 48 - j1; if (d >= 0 && d < DD)
                s_S[(48+d)*WS + rl0] = __float2half_rn(fminf(fmaxf(c1, -10.f), 10.f));
            d = rl1 + 48 - j0; if (d >= 0 && d < DD)
                s_S[(48+d)*WS + rl1] = __float2half_rn(fminf(fmaxf(c2, -10.f), 10.f));
            d = rl1 + 48 - j1; if (d >= 0 && d < DD)
                s_S[(48+d)*WS + rl1] = __float2half_rn(fminf(fmaxf(c3, -10.f), 10.f));
        }
    }
    __syncthreads();

    // Vectorized copy-out: dp<48 -> L d=dp; dp>=48 -> R d=dp-48.
    const int wlim = min(128, WW - u0);          // 128 or 32 (both mult of 8)
    const int obase = (b*3)*DD*HW_ + h*WW + u0;
    for (int i = t; i < 96*16; i += 256) {
        int dp = i >> 4, k = i & 15;
        int w8 = 8*k;
        if (w8 < wlim) {
            int4 v = *(const int4*)&s_S[dp*WS + w8];
            const __half* hv = (const __half*)&v;
            float4 o1, o2;
            o1.x = __half2float(hv[0]); o1.y = __half2float(hv[1]);
            o1.z = __half2float(hv[2]); o1.w = __half2float(hv[3]);
            o2.x = __half2float(hv[4]); o2.y = __half2float(hv[5]);
            o2.z = __half2float(hv[6]); o2.w = __half2float(hv[7]);
            *(float4*)&out[obase + dp*HW_ + w8]     = o1;
            *(float4*)&out[obase + dp*HW_ + w8 + 4] = o2;
        }
    }
}

// ---------------------------------------------------------------------------
extern "C" void kernel_launch(void* const* d_in, const int* in_sizes, int n_in,
                              void* d_out, int out_size)
{
    const float* xl = (const float*)d_in[0];
    const float* xm = (const float*)d_in[1];
    const float* xr = (const float*)d_in[2];
    float* out = (float*)d_out;

    const int smem_g  = (2*GP*TWH + 2*GJ*TWH + DD*US) * (int)sizeof(__half);     // 71424
    const int smem_lr = ((128+176+176)*TWH + 96*WS) * (int)sizeof(__half);       // 64512
    cudaFuncSetAttribute(cv_g_kernel,
        cudaFuncAttributeMaxDynamicSharedMemorySize, smem_g);
    cudaFuncSetAttribute(cv_lrcost_kernel,
        cudaFuncAttributeMaxDynamicSharedMemorySize, smem_lr);

    cv_prep_kernel<<<dim3(HH, BB, 3), 448>>>(xl, xm, xr);
    cv_g_kernel<<<dim3(2, HH, BB), 256, smem_g>>>();
    cv_lr_out_kernel<<<dim3(HH/4, DD, BB), 416>>>(out);
    cv_lrcost_kernel<<<dim3(4, HH, BB), 256, smem_lr>>>(out);
}

// round 13
// speedup vs baseline: 1.5177x; 1.5177x over previous
#include <cuda_runtime.h>
#include <cuda_fp16.h>
#include <cstdint>

#define BB 2
#define CC 32
#define HH 128
#define WW 416
#define DD 48
#define HW_ (HH*WW)
#define CHW_ (CC*HH*WW)
#define ISCALE 0.05892556509887896f  // 1/sqrt(C*K2) = 1/sqrt(288)
#define RP 416    // row stride (halves) for fm16/Al16/Br16
#define PHW 208   // parity half-width

__device__ __forceinline__ float h16(float v) {
    return __half2float(__float2half_rn(v));
}

#define MMA16816(c0,c1,c2,c3,a0,a1,a2,a3,b0,b1) \
  asm volatile("mma.sync.aligned.m16n8k16.row.col.f32.f16.f16.f32 " \
    "{%0,%1,%2,%3}, {%4,%5,%6,%7}, {%8,%9}, {%0,%1,%2,%3};" \
    : "+f"(c0), "+f"(c1), "+f"(c2), "+f"(c3) \
    : "r"(a0), "r"(a1), "r"(a2), "r"(a3), "r"(b0), "r"(b1))

#define LDSM_X4_T(r0,r1,r2,r3,addr) \
  asm volatile("ldmatrix.sync.aligned.m8n8.x4.trans.shared.b16 {%0,%1,%2,%3}, [%4];" \
    : "=r"(r0), "=r"(r1), "=r"(r2), "=r"(r3) : "r"(addr))

__device__ __forceinline__ uint32_t smem_u32(const void* p) {
    return (uint32_t)__cvta_generic_to_shared(p);
}

// Device-global scratch (allocation forbidden)
__device__ __half g_Al16[BB*CC*HH*RP];     // normalized box sums, fp16, [b][c][h][w]
__device__ __half g_Br16[BB*CC*HH*RP];
__device__ __half g_fm16[BB*CC*HH*RP];     // normalized xm * ISCALE
__device__ __half g_xl16[BB*CC*HH*2*PHW];  // parity-split inputs [b][c][h][q][p]
__device__ __half g_xr16[BB*CC*HH*2*PHW];
__device__ float  g_nli[BB*HW_];
__device__ float  g_nri[BB*HW_];
__device__ float  g_Grow[BB*DD*HW_];

// ---------------------------------------------------------------------------
// Kernel 1: prep (proven). z=0/1: box sums + norms + parity-split copies.
// z=2: normalized xm (ISCALE folded).
// ---------------------------------------------------------------------------
__global__ __launch_bounds__(448) void cv_prep_kernel(
    const float* __restrict__ xl, const float* __restrict__ xm,
    const float* __restrict__ xr)
{
    const int t    = threadIdx.x;
    const int wi   = t >> 5;
    const int lane = t & 31;
    const int h    = blockIdx.x;
    const int b    = blockIdx.y;
    const int img  = blockIdx.z;

    const int u = wi*30 + lane - 1;          // -1 .. 419
    const bool vu = (u >= 0) && (u < WW);
    const bool writer = (lane >= 1) && (lane <= 30) && (u < WW);

    if (img == 2) {
        if (writer) {
            float ss = 0.f;
            float fv[CC];
            const float* pm = xm + b*CHW_ + h*WW + u;
            #pragma unroll
            for (int c = 0; c < CC; c++) { fv[c] = __ldg(pm + c*HW_); ss += fv[c]*fv[c]; }
            float nf = ISCALE / fmaxf(sqrtf(ss), 1e-3f);
            #pragma unroll
            for (int c = 0; c < CC; c++)
                g_fm16[((b*CC + c)*HH + h)*RP + u] = __float2half_rn(fv[c]*nf);
        }
        return;
    }

    const float* x = img ? xr : xl;
    __half* gbox   = img ? g_Br16 : g_Al16;
    __half* gq     = img ? g_xr16 : g_xl16;
    float* gn      = img ? g_nri : g_nli;

    const bool h0 = (h > 0), h1 = (h < HH - 1);
    const float* base = x + b*CHW_ + h*WW + (vu ? u : 0);

    float ssum = 0.f;
    float boxv[CC];
    #pragma unroll
    for (int c = 0; c < CC; c++) {
        float r0 = (vu && h0) ? __ldg(base + c*HW_ - WW) : 0.f;
        float r1 =  vu        ? __ldg(base + c*HW_)      : 0.f;
        float r2 = (vu && h1) ? __ldg(base + c*HW_ + WW) : 0.f;
        float cs = r0 + r1 + r2;
        ssum += r0*r0 + r1*r1 + r2*r2;
        if (writer)
            gq[((b*CC + c)*HH + h)*(2*PHW) + (u & 1)*PHW + (u >> 1)] = __float2half_rn(r1);
        float csl = __shfl_up_sync(0xffffffffu, cs, 1);
        float csr = __shfl_down_sync(0xffffffffu, cs, 1);
        boxv[c] = csl + cs + csr;
    }
    float sql = __shfl_up_sync(0xffffffffu, ssum, 1);
    float sqr = __shfl_down_sync(0xffffffffu, ssum, 1);
    float ni = 1.f / fmaxf(sqrtf(sql + ssum + sqr), 1e-3f);

    if (writer) {
        #pragma unroll
        for (int c = 0; c < CC; c++)
            gbox[((b*CC + c)*HH + h)*RP + u] = __float2half_rn(boxv[c] * ni);
        gn[b*HW_ + h*WW + u] = ni;
    }
}

// ---------------------------------------------------------------------------
// Kernel 2: Grow via HMMA + ldmatrix. Natural [c][col] smem; int4 row-copy
// fills; fragments via ldmatrix.x4.trans. Staging [d][u_loc], 3-tap copy-out.
// ---------------------------------------------------------------------------
#define GP  128   // p cols staged per parity
#define GSL 136   // XL stride (halves): 272B, 17c%8 distinct -> LDSM cf
#define GJ  176   // j cols per parity
#define GSR 184   // XR stride: 368B, 23c%8 distinct
#define US  264

__global__ __launch_bounds__(256) void cv_g_kernel()
{
    extern __shared__ __half gsm[];
    __half* s_XL = gsm;                              // [q][c][p_loc]
    __half* s_XR = gsm + 2*CC*GSL;                   // [q][c][j]
    __half* s_G  = gsm + 2*CC*GSL + 2*CC*GSR;        // [d][u_loc]

    const int t  = threadIdx.x;
    const int u0 = blockIdx.x * 208;
    const int r  = blockIdx.y;
    const int b  = blockIdx.z;
    const int P0 = u0/2 - 8;          // multiple of 8
    const int J0 = P0 - 48;           // multiple of 8

    // XL fill: 2 q x 32 c x 16 int4 row copies
    for (int i = t; i < 2*CC*16; i += 256) {
        int k = i & 15, c = (i >> 4) & 31, q = i >> 9;
        int p = P0 + 8*k;
        int4 v = make_int4(0,0,0,0);
        if (p >= 0 && p <= PHW-8)
            v = *(const int4*)&g_xl16[((b*CC + c)*HH + r)*(2*PHW) + q*PHW + p];
        *(int4*)&s_XL[(q*CC + c)*GSL + 8*k] = v;
    }
    // XR fill: 2 q x 32 c x 22 int4
    for (int i = t; i < 2*CC*22; i += 256) {
        int k = i % 22, c = (i/22) % CC, q = i / (22*CC);
        int m0 = J0 + 8*k;
        int4 v = make_int4(0,0,0,0);
        if (m0 >= 0 && m0 <= PHW-8)
            v = *(const int4*)&g_xr16[((b*CC + c)*HH + r)*(2*PHW) + q*PHW + m0];
        *(int4*)&s_XR[(q*CC + c)*GSR + 8*k] = v;
    }
    __syncthreads();

    const int wid  = t >> 5;
    const int lane = t & 31;
    const int g    = lane >> 2;
    const int tt   = lane & 3;
    const int lc   = (lane & 7) + ((lane & 16) >> 1);  // A-frag row (k)
    const int lm   = lane & 8;                          // A-frag col offset

    for (int job = wid; job < 16; job += 8) {
        const int q = job & 1;
        const int i = job >> 1;                   // m-tile 0..7
        const uint32_t XLq = smem_u32(s_XL + q*CC*GSL);
        const uint32_t XRq = smem_u32(s_XR + q*CC*GSR);

        const int rl0 = 16*i + g, rl1 = rl0 + 8;  // p_loc rows of results
        uint32_t a0,a1,a2,a3,a4,a5,a6,a7;
        {
            uint32_t ad0 = XLq + (uint32_t)((lc)*GSL + 16*i + lm) * 2;
            uint32_t ad1 = ad0 + 16*GSL*2;
            LDSM_X4_T(a0,a1,a2,a3, ad0);
            LDSM_X4_T(a4,a5,a6,a7, ad1);
        }

        const int ub0 = 2*rl0 + q;                // u_loc of rl0
        const int ub1 = 2*rl1 + q;

        #pragma unroll
        for (int nn = 0; nn < 8; nn++) {
            const int jbase = 16*i + 8*nn;
            uint32_t b0,b1,b2,b3;
            LDSM_X4_T(b0,b1,b2,b3, XRq + (uint32_t)(lane*GSR + jbase)*2);
            float c0 = 0.f, c1 = 0.f, c2 = 0.f, c3 = 0.f;
            MMA16816(c0,c1,c2,c3, a0,a1,a2,a3, b0,b1);
            MMA16816(c0,c1,c2,c3, a4,a5,a6,a7, b2,b3);
            const int j0 = jbase + 2*tt, j1 = j0 + 1;
            int d;
            d = rl0 + 48 - j0; if (d >= 0 && d < DD) s_G[d*US + ub0] = __float2half_rn(c0);
            d = rl0 + 48 - j1; if (d >= 0 && d < DD) s_G[d*US + ub0] = __float2half_rn(c1);
            d = rl1 + 48 - j0; if (d >= 0 && d < DD) s_G[d*US + ub1] = __float2half_rn(c2);
            d = rl1 + 48 - j1; if (d >= 0 && d < DD) s_G[d*US + ub1] = __float2half_rn(c3);
        }
    }
    __syncthreads();

    // Horizontal 3-tap + vectorized store. u = u0 + ul, u_loc = ul + 16.
    for (int i = t; i < DD*52; i += 256) {
        int d = i / 52, k4 = (i % 52) * 4;
        int base = d*US + 16 + k4;
        __half2 q0 = *(const __half2*)(s_G + base - 2);
        __half2 q1 = *(const __half2*)(s_G + base);
        __half2 q2 = *(const __half2*)(s_G + base + 2);
        __half2 q3 = *(const __half2*)(s_G + base + 4);
        float gm1 = __high2float(q0);
        float g0  = __low2float(q1), g1 = __high2float(q1);
        float g2  = __low2float(q2), g3 = __high2float(q2);
        float g4  = __low2float(q3);
        float4 o;
        o.x = gm1 + g0 + g1;
        o.y = g0 + g1 + g2;
        o.z = g1 + g2 + g3;
        o.w = g2 + g3 + g4;
        *(float4*)&g_Grow[(b*DD + d)*HW_ + r*WW + u0 + k4] = o;
    }
}

// ---------------------------------------------------------------------------
// Kernel 3: LR channel -- vertical 3-tap over Grow + normalization (proven).
// ---------------------------------------------------------------------------
__global__ __launch_bounds__(416) void cv_lr_out_kernel(float* __restrict__ out)
{
    const int w  = threadIdx.x;
    const int h0 = blockIdx.x * 4;
    const int d  = blockIdx.y;
    const int b  = blockIdx.z;

    const int ob = (b*3 + 2)*DD*HW_ + d*HW_ + w;
    if (w < d || w >= WW - d) {
        #pragma unroll
        for (int r = 0; r < 4; r++) out[ob + (h0+r)*WW] = 0.f;
        return;
    }
    const int u = w + d;
    const float* gb = g_Grow + (b*DD + d)*HW_ + u;

    float v[6];
    #pragma unroll
    for (int r = 0; r < 6; r++) {
        int row = h0 - 1 + r;
        v[r] = (row >= 0 && row < HH) ? __ldg(gb + row*WW) : 0.f;
    }
    const float* pnl = g_nli + b*HW_ + u;
    const float* pnr = g_nri + b*HW_ + (w - d);
    #pragma unroll
    for (int r = 0; r < 4; r++) {
        int h = h0 + r;
        float s = v[r] + v[r+1] + v[r+2];
        float val = s * __ldg(pnl + h*WW) * __ldg(pnr + h*WW) * ISCALE;
        out[ob + h*WW] = h16(fminf(fmaxf(val, -10.f), 10.f));
    }
}

// ---------------------------------------------------------------------------
// Kernel 4: L/R channels via HMMA + ldmatrix. Natural [c][col] smem,
// int4 row-copy fills, R11's proven staging epilogue ([w][dp], WS2=98).
// ---------------------------------------------------------------------------
#define FS  136   // F stride (halves)
#define WSJ 184   // WA/WB stride
#define WS2 98    // staging stride

__global__ __launch_bounds__(256) void cv_lrcost_kernel(float* __restrict__ out)
{
    extern __shared__ __half lsm[];
    __half* s_F  = lsm;                          // [c][w_local]   32x136
    __half* s_WA = lsm + CC*FS;                  // [c][j]         32x184
    __half* s_WB = lsm + CC*FS + CC*WSJ;         // [c][j]
    __half* s_S  = lsm + CC*FS + 2*CC*WSJ;       // [w][dp]        128x98

    const int t  = threadIdx.x;
    const int u0 = blockIdx.x * 128;
    const int h  = blockIdx.y;
    const int b  = blockIdx.z;

    // F fill: 32 c x 16 int4
    for (int i = t; i < CC*16; i += 256) {
        int c = i >> 4, k = i & 15;
        int col = u0 + 8*k;
        int4 v = make_int4(0,0,0,0);
        if (col <= WW-8) v = *(const int4*)&g_fm16[((b*CC + c)*HH + h)*RP + col];
        *(int4*)&s_F[c*FS + 8*k] = v;
    }
    // WA fill: 32 c x 22 int4
    for (int i = t; i < CC*22; i += 256) {
        int c = i / 22, k = i % 22;
        int col = u0 + 8*k;
        int4 v = make_int4(0,0,0,0);
        if (col <= WW-8) v = *(const int4*)&g_Al16[((b*CC + c)*HH + h)*RP + col];
        *(int4*)&s_WA[c*WSJ + 8*k] = v;
    }
    // WB fill: 32 c x 22 int4
    for (int i = t; i < CC*22; i += 256) {
        int c = i / 22, k = i % 22;
        int col = u0 - 48 + 8*k;
        int4 v = make_int4(0,0,0,0);
        if (col >= 0 && col <= WW-8)
            v = *(const int4*)&g_Br16[((b*CC + c)*HH + h)*RP + col];
        *(int4*)&s_WB[c*WSJ + 8*k] = v;
    }
    __syncthreads();

    const int wid  = t >> 5;
    const int lane = t & 31;
    const int g    = lane >> 2;
    const int tt   = lane & 3;
    const int wl0  = wid * 16;
    const int lc   = (lane & 7) + ((lane & 16) >> 1);
    const int lm   = lane & 8;

    uint32_t a0,a1,a2,a3,a4,a5,a6,a7;
    {
        uint32_t ad0 = smem_u32(s_F) + (uint32_t)(lc*FS + wl0 + lm) * 2;
        uint32_t ad1 = ad0 + 16*FS*2;
        LDSM_X4_T(a0,a1,a2,a3, ad0);
        LDSM_X4_T(a4,a5,a6,a7, ad1);
    }

    const uint32_t WAb = smem_u32(s_WA) + (uint32_t)(lane*WSJ)*2;
    const uint32_t WBb = smem_u32(s_WB) + (uint32_t)(lane*WSJ)*2;
    const int rl0 = wl0 + g, rl1 = rl0 + 8;
    const int sb0 = rl0 * WS2, sb1 = rl1 * WS2;

    #pragma unroll
    for (int nn = 0; nn < 8; nn++) {
        const int jbase = wl0 + 8*nn;
        const int j0 = jbase + 2*tt, j1 = j0 + 1;

        {   // L side: dp = j - rl
            uint32_t b0,b1,b2,b3;
            LDSM_X4_T(b0,b1,b2,b3, WAb + (uint32_t)jbase*2);
            float c0 = 0.f, c1 = 0.f, c2 = 0.f, c3 = 0.f;
            MMA16816(c0,c1,c2,c3, a0,a1,a2,a3, b0,b1);
            MMA16816(c0,c1,c2,c3, a4,a5,a6,a7, b2,b3);
            int d;
            d = j0 - rl0; if (d >= 0 && d < DD)
                s_S[sb0 + d] = __float2half_rn(fminf(fmaxf(c0, -10.f), 10.f));
            d = j1 - rl0; if (d >= 0 && d < DD)
                s_S[sb0 + d] = __float2half_rn(fminf(fmaxf(c1, -10.f), 10.f));
            d = j0 - rl1; if (d >= 0 && d < DD)
                s_S[sb1 + d] = __float2half_rn(fminf(fmaxf(c2, -10.f), 10.f));
            d = j1 - rl1; if (d >= 0 && d < DD)
                s_S[sb1 + d] = __float2half_rn(fminf(fmaxf(c3, -10.f), 10.f));
        }
        {   // R side: dp = 48 + (rl + 48 - j)
            uint32_t b0,b1,b2,b3;
            LDSM_X4_T(b0,b1,b2,b3, WBb + (uint32_t)jbase*2);
            float c0 = 0.f, c1 = 0.f, c2 = 0.f, c3 = 0.f;
            MMA16816(c0,c1,c2,c3, a0,a1,a2,a3, b0,b1);
            MMA16816(c0,c1,c2,c3, a4,a5,a6,a7, b2,b3);
            int d;
            d = rl0 + 48 - j0; if (d >= 0 && d < DD)
                s_S[sb0 + 48 + d] = __float2half_rn(fminf(fmaxf(c0, -10.f), 10.f));
            d = rl0 + 48 - j1; if (d >= 0 && d < DD)
                s_S[sb0 + 48 + d] = __float2half_rn(fminf(fmaxf(c1, -10.f), 10.f));
            d = rl1 + 48 - j0; if (d >= 0 && d < DD)
                s_S[sb1 + 48 + d] = __float2half_rn(fminf(fmaxf(c2, -10.f), 10.f));
            d = rl1 + 48 - j1; if (d >= 0 && d < DD)
                s_S[sb1 + 48 + d] = __float2half_rn(fminf(fmaxf(c3, -10.f), 10.f));
        }
    }
    __syncthreads();

    // Copy-out (conflict-free: stride 49 words, 17w%32 distinct).
    const int wlim = min(128, WW - u0);
    const int obase = (b*3)*DD*HW_ + h*WW + u0;
    for (int i = t; i < 96*128; i += 256) {
        int dp = i >> 7, w = i & 127;
        if (w < wlim)
            out[obase + dp*HW_ + w] = __half2float(s_S[w*WS2 + dp]);
    }
}

// ---------------------------------------------------------------------------
extern "C" void kernel_launch(void* const* d_in, const int* in_sizes, int n_in,
                              void* d_out, int out_size)
{
    const float* xl = (const float*)d_in[0];
    const float* xm = (const float*)d_in[1];
    const float* xr = (const float*)d_in[2];
    float* out = (float*)d_out;

    const int smem_g  = (2*CC*GSL + 2*CC*GSR + DD*US) * (int)sizeof(__half);     // 66304
    const int smem_lr = (CC*FS + 2*CC*WSJ + 128*WS2) * (int)sizeof(__half);      // 57344
    cudaFuncSetAttribute(cv_g_kernel,
        cudaFuncAttributeMaxDynamicSharedMemorySize, smem_g);
    cudaFuncSetAttribute(cv_lrcost_kernel,
        cudaFuncAttributeMaxDynamicSharedMemorySize, smem_lr);

    cv_prep_kernel<<<dim3(HH, BB, 3), 448>>>(xl, xm, xr);
    cv_g_kernel<<<dim3(2, HH, BB), 256, smem_g>>>();
    cv_lr_out_kernel<<<dim3(HH/4, DD, BB), 416>>>(out);
    cv_lrcost_kernel<<<dim3(4, HH, BB), 256, smem_lr>>>(out);
}

// round 14
// speedup vs baseline: 1.6792x; 1.1064x over previous
#include <cuda_runtime.h>
#include <cuda_fp16.h>
#include <cstdint>

#define BB 2
#define CC 32
#define HH 128
#define WW 416
#define DD 48
#define HW_ (HH*WW)
#define CHW_ (CC*HH*WW)
#define ISCALE 0.05892556509887896f  // 1/sqrt(C*K2) = 1/sqrt(288)
#define RP 416    // row stride (halves) for Al16/Br16
#define PHW 208   // parity half-width

__device__ __forceinline__ float h16(float v) {
    return __half2float(__float2half_rn(v));
}

#define MMA16816(c0,c1,c2,c3,a0,a1,a2,a3,b0,b1) \
  asm volatile("mma.sync.aligned.m16n8k16.row.col.f32.f16.f16.f32 " \
    "{%0,%1,%2,%3}, {%4,%5,%6,%7}, {%8,%9}, {%0,%1,%2,%3};" \
    : "+f"(c0), "+f"(c1), "+f"(c2), "+f"(c3) \
    : "r"(a0), "r"(a1), "r"(a2), "r"(a3), "r"(b0), "r"(b1))

#define LDSM_X4_T(r0,r1,r2,r3,addr) \
  asm volatile("ldmatrix.sync.aligned.m8n8.x4.trans.shared.b16 {%0,%1,%2,%3}, [%4];" \
    : "=r"(r0), "=r"(r1), "=r"(r2), "=r"(r3) : "r"(addr))

__device__ __forceinline__ uint32_t smem_u32(const void* p) {
    return (uint32_t)__cvta_generic_to_shared(p);
}

// Device-global scratch (allocation forbidden)
__device__ __half g_Al16[BB*CC*HH*RP];     // RAW 3x3 box sums, fp16, [b][c][h][w]
__device__ __half g_Br16[BB*CC*HH*RP];
__device__ __half g_xl16[BB*CC*HH*2*PHW];  // parity-split inputs [b][c][h][q][p]
__device__ __half g_xr16[BB*CC*HH*2*PHW];
__device__ float  g_nli[BB*HW_];           // plain 1/max(||patch||, eps)
__device__ float  g_nri[BB*HW_];
__device__ float  g_Grow[BB*DD*HW_];

// ---------------------------------------------------------------------------
// Kernel 1: prep. 4 columns/thread, float4 loads. Writes RAW box sums (fp16),
// parity-split input copies (fp16), and patch norms (fp32). No smem.
// ---------------------------------------------------------------------------
__global__ __launch_bounds__(128) void cv_prep_kernel(
    const float* __restrict__ xl, const float* __restrict__ xr)
{
    const int t    = threadIdx.x;
    const int wi   = t >> 5;
    const int lane = t & 31;
    const int h    = blockIdx.x;
    const int b    = blockIdx.y;
    const int img  = blockIdx.z;
    const float* x = img ? xr : xl;
    __half* gbox   = img ? g_Br16 : g_Al16;
    __half* gq     = img ? g_xr16 : g_xl16;
    float* gn      = img ? g_nri : g_nli;

    const int cu = wi*120 + (lane - 1)*4;      // -4 .. 484, multiple of 4
    const bool ld = (cu >= 0) && (cu <= WW - 4);
    const bool wr = (lane >= 1) && (lane <= 30) && (cu <= WW - 4);
    const bool hm = (h > 0), hp = (h < HH - 1);
    const float* base = x + b*CHW_ + h*WW + (ld ? cu : 0);

    float sq0 = 0.f, sq1 = 0.f, sq2 = 0.f, sq3 = 0.f;
    const float4 z4 = make_float4(0.f, 0.f, 0.f, 0.f);

    #pragma unroll
    for (int c = 0; c < CC; c++) {
        float4 r0 = (ld && hm) ? *(const float4*)(base + c*HW_ - WW) : z4;
        float4 r1 =  ld        ? *(const float4*)(base + c*HW_)      : z4;
        float4 r2 = (ld && hp) ? *(const float4*)(base + c*HW_ + WW) : z4;
        float cs0 = r0.x + r1.x + r2.x;
        float cs1 = r0.y + r1.y + r2.y;
        float cs2 = r0.z + r1.z + r2.z;
        float cs3 = r0.w + r1.w + r2.w;
        sq0 += r0.x*r0.x + r1.x*r1.x + r2.x*r2.x;
        sq1 += r0.y*r0.y + r1.y*r1.y + r2.y*r2.y;
        sq2 += r0.z*r0.z + r1.z*r1.z + r2.z*r2.z;
        sq3 += r0.w*r0.w + r1.w*r1.w + r2.w*r2.w;
        float csm1 = __shfl_up_sync(0xffffffffu, cs3, 1);
        float csp1 = __shfl_down_sync(0xffffffffu, cs0, 1);
        if (wr) {
            __half2 b01 = __floats2half2_rn(csm1 + cs0 + cs1, cs0 + cs1 + cs2);
            __half2 b23 = __floats2half2_rn(cs1 + cs2 + cs3, cs2 + cs3 + csp1);
            uint2 bv;
            bv.x = *(const uint32_t*)&b01;
            bv.y = *(const uint32_t*)&b23;
            *(uint2*)&gbox[((b*CC + c)*HH + h)*RP + cu] = bv;
            // parity copies of the center row
            int qb = ((b*CC + c)*HH + h)*(2*PHW) + (cu >> 1);
            *(__half2*)&gq[qb]       = __floats2half2_rn(r1.x, r1.z);  // even
            *(__half2*)&gq[qb + PHW] = __floats2half2_rn(r1.y, r1.w);  // odd
        }
    }
    float sqm1 = __shfl_up_sync(0xffffffffu, sq3, 1);
    float sqp1 = __shfl_down_sync(0xffffffffu, sq0, 1);
    if (wr) {
        float4 n;
        n.x = 1.f / fmaxf(sqrtf(sqm1 + sq0 + sq1), 1e-3f);
        n.y = 1.f / fmaxf(sqrtf(sq0 + sq1 + sq2), 1e-3f);
        n.z = 1.f / fmaxf(sqrtf(sq1 + sq2 + sq3), 1e-3f);
        n.w = 1.f / fmaxf(sqrtf(sq2 + sq3 + sqp1), 1e-3f);
        *(float4*)&gn[b*HW_ + h*WW + cu] = n;
    }
}

// ---------------------------------------------------------------------------
// Kernel 2: Grow via HMMA + ldmatrix (unchanged, proven).
// ---------------------------------------------------------------------------
#define GSL 136
#define GSR 184
#define US  264

__global__ __launch_bounds__(256) void cv_g_kernel()
{
    extern __shared__ __half gsm[];
    __half* s_XL = gsm;                              // [q][c][p_loc]
    __half* s_XR = gsm + 2*CC*GSL;                   // [q][c][j]
    __half* s_G  = gsm + 2*CC*GSL + 2*CC*GSR;        // [d][u_loc]

    const int t  = threadIdx.x;
    const int u0 = blockIdx.x * 208;
    const int r  = blockIdx.y;
    const int b  = blockIdx.z;
    const int P0 = u0/2 - 8;
    const int J0 = P0 - 48;

    for (int i = t; i < 2*CC*16; i += 256) {
        int k = i & 15, c = (i >> 4) & 31, q = i >> 9;
        int p = P0 + 8*k;
        int4 v = make_int4(0,0,0,0);
        if (p >= 0 && p <= PHW-8)
            v = *(const int4*)&g_xl16[((b*CC + c)*HH + r)*(2*PHW) + q*PHW + p];
        *(int4*)&s_XL[(q*CC + c)*GSL + 8*k] = v;
    }
    for (int i = t; i < 2*CC*22; i += 256) {
        int k = i % 22, c = (i/22) % CC, q = i / (22*CC);
        int m0 = J0 + 8*k;
        int4 v = make_int4(0,0,0,0);
        if (m0 >= 0 && m0 <= PHW-8)
            v = *(const int4*)&g_xr16[((b*CC + c)*HH + r)*(2*PHW) + q*PHW + m0];
        *(int4*)&s_XR[(q*CC + c)*GSR + 8*k] = v;
    }
    __syncthreads();

    const int wid  = t >> 5;
    const int lane = t & 31;
    const int g    = lane >> 2;
    const int tt   = lane & 3;
    const int lc   = (lane & 7) + ((lane & 16) >> 1);
    const int lm   = lane & 8;

    for (int job = wid; job < 16; job += 8) {
        const int q = job & 1;
        const int i = job >> 1;
        const uint32_t XLq = smem_u32(s_XL + q*CC*GSL);
        const uint32_t XRq = smem_u32(s_XR + q*CC*GSR);

        const int rl0 = 16*i + g, rl1 = rl0 + 8;
        uint32_t a0,a1,a2,a3,a4,a5,a6,a7;
        {
            uint32_t ad0 = XLq + (uint32_t)((lc)*GSL + 16*i + lm) * 2;
            uint32_t ad1 = ad0 + 16*GSL*2;
            LDSM_X4_T(a0,a1,a2,a3, ad0);
            LDSM_X4_T(a4,a5,a6,a7, ad1);
        }
        const int ub0 = 2*rl0 + q;
        const int ub1 = 2*rl1 + q;

        #pragma unroll
        for (int nn = 0; nn < 8; nn++) {
            const int jbase = 16*i + 8*nn;
            uint32_t b0,b1,b2,b3;
            LDSM_X4_T(b0,b1,b2,b3, XRq + (uint32_t)(lane*GSR + jbase)*2);
            float c0 = 0.f, c1 = 0.f, c2 = 0.f, c3 = 0.f;
            MMA16816(c0,c1,c2,c3, a0,a1,a2,a3, b0,b1);
            MMA16816(c0,c1,c2,c3, a4,a5,a6,a7, b2,b3);
            const int j0 = jbase + 2*tt, j1 = j0 + 1;
            int d;
            d = rl0 + 48 - j0; if (d >= 0 && d < DD) s_G[d*US + ub0] = __float2half_rn(c0);
            d = rl0 + 48 - j1; if (d >= 0 && d < DD) s_G[d*US + ub0] = __float2half_rn(c1);
            d = rl1 + 48 - j0; if (d >= 0 && d < DD) s_G[d*US + ub1] = __float2half_rn(c2);
            d = rl1 + 48 - j1; if (d >= 0 && d < DD) s_G[d*US + ub1] = __float2half_rn(c3);
        }
    }
    __syncthreads();

    for (int i = t; i < DD*52; i += 256) {
        int d = i / 52, k4 = (i % 52) * 4;
        int base = d*US + 16 + k4;
        __half2 q0 = *(const __half2*)(s_G + base - 2);
        __half2 q1 = *(const __half2*)(s_G + base);
        __half2 q2 = *(const __half2*)(s_G + base + 2);
        __half2 q3 = *(const __half2*)(s_G + base + 4);
        float gm1 = __high2float(q0);
        float g0  = __low2float(q1), g1 = __high2float(q1);
        float g2  = __low2float(q2), g3 = __high2float(q2);
        float g4  = __low2float(q3);
        float4 o;
        o.x = gm1 + g0 + g1;
        o.y = g0 + g1 + g2;
        o.z = g1 + g2 + g3;
        o.w = g2 + g3 + g4;
        *(float4*)&g_Grow[(b*DD + d)*HW_ + r*WW + u0 + k4] = o;
    }
}

// ---------------------------------------------------------------------------
// Kernel 3: LR channel -- vertical 3-tap over Grow + normalization (proven).
// ---------------------------------------------------------------------------
__global__ __launch_bounds__(416) void cv_lr_out_kernel(float* __restrict__ out)
{
    const int w  = threadIdx.x;
    const int h0 = blockIdx.x * 4;
    const int d  = blockIdx.y;
    const int b  = blockIdx.z;

    const int ob = (b*3 + 2)*DD*HW_ + d*HW_ + w;
    if (w < d || w >= WW - d) {
        #pragma unroll
        for (int r = 0; r < 4; r++) out[ob + (h0+r)*WW] = 0.f;
        return;
    }
    const int u = w + d;
    const float* gb = g_Grow + (b*DD + d)*HW_ + u;

    float v[6];
    #pragma unroll
    for (int r = 0; r < 6; r++) {
        int row = h0 - 1 + r;
        v[r] = (row >= 0 && row < HH) ? __ldg(gb + row*WW) : 0.f;
    }
    const float* pnl = g_nli + b*HW_ + u;
    const float* pnr = g_nri + b*HW_ + (w - d);
    #pragma unroll
    for (int r = 0; r < 4; r++) {
        int h = h0 + r;
        float s = v[r] + v[r+1] + v[r+2];
        float val = s * __ldg(pnl + h*WW) * __ldg(pnr + h*WW) * ISCALE;
        out[ob + h*WW] = h16(fminf(fmaxf(val, -10.f), 10.f));
    }
}

// ---------------------------------------------------------------------------
// Kernel 4: L/R channels via HMMA + ldmatrix. fm computed in-kernel from xm
// (normalized, ISCALE folded); RAW box operands; per-column norms applied
// at band-extract. Staging epilogue [w][dp] (proven).
// ---------------------------------------------------------------------------
#define FS  136
#define WSJ 184
#define WS2 98

__global__ __launch_bounds__(256) void cv_lrcost_kernel(
    const float* __restrict__ xm, float* __restrict__ out)
{
    extern __shared__ __half lsm[];
    __half* s_F  = lsm;                          // [c][w_local]
    __half* s_WA = lsm + CC*FS;                  // [c][j]
    __half* s_WB = lsm + CC*FS + CC*WSJ;         // [c][j]
    __half* s_S  = lsm + CC*FS + 2*CC*WSJ;       // [w][dp]
    float*  s_nA = (float*)(lsm + CC*FS + 2*CC*WSJ + 128*WS2);  // [176]
    float*  s_nB = s_nA + 176;

    const int t  = threadIdx.x;
    const int u0 = blockIdx.x * 128;
    const int h  = blockIdx.y;
    const int b  = blockIdx.z;

    // WA fill: 32 c x 22 int4 (raw box sums)
    for (int i = t; i < CC*22; i += 256) {
        int c = i / 22, k = i % 22;
        int col = u0 + 8*k;
        int4 v = make_int4(0,0,0,0);
        if (col <= WW-8) v = *(const int4*)&g_Al16[((b*CC + c)*HH + h)*RP + col];
        *(int4*)&s_WA[c*WSJ + 8*k] = v;
    }
    // WB fill
    for (int i = t; i < CC*22; i += 256) {
        int c = i / 22, k = i % 22;
        int col = u0 - 48 + 8*k;
        int4 v = make_int4(0,0,0,0);
        if (col >= 0 && col <= WW-8)
            v = *(const int4*)&g_Br16[((b*CC + c)*HH + h)*RP + col];
        *(int4*)&s_WB[c*WSJ + 8*k] = v;
    }
    // norm fills
    for (int j = t; j < 176; j += 256) {
        int colA = u0 + j;
        s_nA[j] = (colA < WW) ? g_nli[b*HW_ + h*WW + colA] : 0.f;
        int colB = u0 - 48 + j;
        s_nB[j] = (colB >= 0 && colB < WW) ? g_nri[b*HW_ + h*WW + colB] : 0.f;
    }
    // fm fill: compute normalized xm (ISCALE folded) directly
    if (t < 128) {
        const int w = u0 + t;
        float fv[CC];
        float ss = 0.f;
        if (w < WW) {
            const float* pm = xm + b*CHW_ + h*WW + w;
            #pragma unroll
            for (int c = 0; c < CC; c++) { fv[c] = __ldg(pm + c*HW_); ss += fv[c]*fv[c]; }
        } else {
            #pragma unroll
            for (int c = 0; c < CC; c++) fv[c] = 0.f;
        }
        float nf = ISCALE / fmaxf(sqrtf(ss), 1e-3f);
        #pragma unroll
        for (int c = 0; c < CC; c++)
            s_F[c*FS + t] = __float2half_rn(fv[c]*nf);
    }
    __syncthreads();

    const int wid  = t >> 5;
    const int lane = t & 31;
    const int g    = lane >> 2;
    const int tt   = lane & 3;
    const int wl0  = wid * 16;
    const int lc   = (lane & 7) + ((lane & 16) >> 1);
    const int lm   = lane & 8;

    uint32_t a0,a1,a2,a3,a4,a5,a6,a7;
    {
        uint32_t ad0 = smem_u32(s_F) + (uint32_t)(lc*FS + wl0 + lm) * 2;
        uint32_t ad1 = ad0 + 16*FS*2;
        LDSM_X4_T(a0,a1,a2,a3, ad0);
        LDSM_X4_T(a4,a5,a6,a7, ad1);
    }

    const uint32_t WAb = smem_u32(s_WA) + (uint32_t)(lane*WSJ)*2;
    const uint32_t WBb = smem_u32(s_WB) + (uint32_t)(lane*WSJ)*2;
    const int rl0 = wl0 + g, rl1 = rl0 + 8;
    const int sb0 = rl0 * WS2, sb1 = rl1 * WS2;

    #pragma unroll
    for (int nn = 0; nn < 8; nn++) {
        const int jbase = wl0 + 8*nn;
        const int j0 = jbase + 2*tt, j1 = j0 + 1;

        {   // L side: dp = j - rl, multiplier = nli at col u0+j
            uint32_t b0,b1,b2,b3;
            LDSM_X4_T(b0,b1,b2,b3, WAb + (uint32_t)jbase*2);
            float c0 = 0.f, c1 = 0.f, c2 = 0.f, c3 = 0.f;
            MMA16816(c0,c1,c2,c3, a0,a1,a2,a3, b0,b1);
            MMA16816(c0,c1,c2,c3, a4,a5,a6,a7, b2,b3);
            float fa0 = s_nA[j0], fa1 = s_nA[j1];
            int d;
            d = j0 - rl0; if (d >= 0 && d < DD)
                s_S[sb0 + d] = __float2half_rn(fminf(fmaxf(c0*fa0, -10.f), 10.f));
            d = j1 - rl0; if (d >= 0 && d < DD)
                s_S[sb0 + d] = __float2half_rn(fminf(fmaxf(c1*fa1, -10.f), 10.f));
            d = j0 - rl1; if (d >= 0 && d < DD)
                s_S[sb1 + d] = __float2half_rn(fminf(fmaxf(c2*fa0, -10.f), 10.f));
            d = j1 - rl1; if (d >= 0 && d < DD)
                s_S[sb1 + d] = __float2half_rn(fminf(fmaxf(c3*fa1, -10.f), 10.f));
        }
        {   // R side: dp = 48 + (rl + 48 - j), multiplier = nri at col u0-48+j
            uint32_t b0,b1,b2,b3;
            LDSM_X4_T(b0,b1,b2,b3, WBb + (uint32_t)jbase*2);
            float c0 = 0.f, c1 = 0.f, c2 = 0.f, c3 = 0.f;
            MMA16816(c0,c1,c2,c3, a0,a1,a2,a3, b0,b1);
            MMA16816(c0,c1,c2,c3, a4,a5,a6,a7, b2,b3);
            float fb0 = s_nB[j0], fb1 = s_nB[j1];
            int d;
            d = rl0 + 48 - j0; if (d >= 0 && d < DD)
                s_S[sb0 + 48 + d] = __float2half_rn(fminf(fmaxf(c0*fb0, -10.f), 10.f));
            d = rl0 + 48 - j1; if (d >= 0 && d < DD)
                s_S[sb0 + 48 + d] = __float2half_rn(fminf(fmaxf(c1*fb1, -10.f), 10.f));
            d = rl1 + 48 - j0; if (d >= 0 && d < DD)
                s_S[sb1 + 48 + d] = __float2half_rn(fminf(fmaxf(c2*fb0, -10.f), 10.f));
            d = rl1 + 48 - j1; if (d >= 0 && d < DD)
                s_S[sb1 + 48 + d] = __float2half_rn(fminf(fmaxf(c3*fb1, -10.f), 10.f));
        }
    }
    __syncthreads();

    const int wlim = min(128, WW - u0);
    const int obase = (b*3)*DD*HW_ + h*WW + u0;
    for (int i = t; i < 96*128; i += 256) {
        int dp = i >> 7, w = i & 127;
        if (w < wlim)
            out[obase + dp*HW_ + w] = __half2float(s_S[w*WS2 + dp]);
    }
}

// ---------------------------------------------------------------------------
extern "C" void kernel_launch(void* const* d_in, const int* in_sizes, int n_in,
                              void* d_out, int out_size)
{
    const float* xl = (const float*)d_in[0];
    const float* xm = (const float*)d_in[1];
    const float* xr = (const float*)d_in[2];
    float* out = (float*)d_out;

    const int smem_g  = (2*CC*GSL + 2*CC*GSR + DD*US) * (int)sizeof(__half);          // 66304
    const int smem_lr = (CC*FS + 2*CC*WSJ + 128*WS2) * (int)sizeof(__half)
                        + 2*176*(int)sizeof(float);                                    // 58752
    cudaFuncSetAttribute(cv_g_kernel,
        cudaFuncAttributeMaxDynamicSharedMemorySize, smem_g);
    cudaFuncSetAttribute(cv_lrcost_kernel,
        cudaFuncAttributeMaxDynamicSharedMemorySize, smem_lr);

    cv_prep_kernel<<<dim3(HH, BB, 2), 128>>>(xl, xr);
    cv_g_kernel<<<dim3(2, HH, BB), 256, smem_g>>>();
    cv_lr_out_kernel<<<dim3(HH/4, DD, BB), 416>>>(out);
    cv_lrcost_kernel<<<dim3(4, HH, BB), 256, smem_lr>>>(xm, out);
}